// round 5
// baseline (speedup 1.0000x reference)
#include <cuda_runtime.h>

// ---------------- grid geometry: one block = (image, channel-group), 409.6KB each ----
// L0: S=80, C=128, CPB=8   -> 16 img * 16 groups = 256 blocks
// L1: S=40, C=256, CPB=32  -> 16 img *  8 groups = 128 blocks
// L2: S=20, C=512, CPB=128 -> 16 img *  4 groups =  64 blocks
#define NB0 256
#define NB1 128
#define NB2 64
#define NB_TOT (NB0 + NB1 + NB2)   // 448

// ---------------- scratch ----------------
__device__ double g_part_sq[NB_TOT];
__device__ double g_part_m[NB_TOT];    // nonzero only for channel-group 0 blocks
__device__ int    g_counter = 0;       // reset by the last block every call

// ---------------- block reduce (valid in thread 0) ----------------
__device__ __forceinline__ float block_reduce(float v) {
    #pragma unroll
    for (int o = 16; o > 0; o >>= 1) v += __shfl_down_sync(0xffffffffu, v, o);
    __shared__ float ws[8];
    const int lane = threadIdx.x & 31, wid = threadIdx.x >> 5;
    if (lane == 0) ws[wid] = v;
    __syncthreads();
    if (wid == 0) {
        v = (lane < 8) ? ws[lane] : 0.0f;
        #pragma unroll
        for (int o = 4; o > 0; o >>= 1) v += __shfl_down_sync(0xffffffffu, v, o);
    }
    return v;
}

// ---------------- per-level worker ----------------
template <int S, int C, int CPB>
__device__ __forceinline__ void level_work(
    const float* __restrict__ p, const float* __restrict__ t,
    const float* __restrict__ bboxes, const int* __restrict__ bidx, int nbox,
    int b, int cg, float* __restrict__ s_mask)
{
    constexpr int HW  = S * S;
    constexpr int HW4 = HW / 4;
    const int tid = threadIdx.x;

    // ---- cache this image's boxes ----
    __shared__ int   cnt;
    __shared__ float s_xc[64], s_yc[64], s_iw[64], s_ih[64];
    __shared__ int   s_xl[64], s_xr[64], s_yt[64], s_yd[64];
    if (tid == 0) cnt = 0;
    __syncthreads();
    for (int i = tid; i < nbox; i += blockDim.x) {
        if (bidx[i] == b) {
            int xc = (int)floorf(bboxes[4 * i + 0] * (float)S);
            int yc = (int)floorf(bboxes[4 * i + 1] * (float)S);
            int w  = (int)floorf(bboxes[4 * i + 2] * (float)S);
            int h  = (int)floorf(bboxes[4 * i + 3] * (float)S);
            int xl = max(xc - w / 2, 0), xr = min(xc + w / 2, S - 1);
            int yt = max(yc - h / 2, 0), yd = min(yc + h / 2, S - 1);
            float wd = (float)(xr - xl + 1), ht = (float)(yd - yt + 1);
            int q = atomicAdd(&cnt, 1);
            s_xc[q] = (float)xc; s_yc[q] = (float)yc;
            // STD^2*(w/2)^2 == w^2 for STD=2
            s_iw[q] = 1.0f / (wd * wd); s_ih[q] = 1.0f / (ht * ht);
            s_xl[q] = xl; s_xr[q] = xr; s_yt[q] = yt; s_yd[q] = yd;
        }
    }
    __syncthreads();
    const int n = cnt;

    // ---- build mask for the whole plane into shared ----
    float msum = 0.0f;
    for (int pix = tid; pix < HW; pix += 256) {
        const int y = pix / S, x = pix % S;
        const float fx = (float)x, fy = (float)y;
        float m = 0.0f;
        for (int i = 0; i < n; i++) {
            if (x >= s_xl[i] && x <= s_xr[i] && y >= s_yt[i] && y <= s_yd[i]) {
                float dx = fx - s_xc[i], dy = fy - s_yc[i];
                float v = __expf(-(dx * dx * s_iw[i] + dy * dy * s_ih[i]));
                m = fmaxf(m, v);
            }
        }
        s_mask[pix] = m;
        msum += m;
    }
    __syncthreads();

    // ---- stream the contiguous channel-group region ----
    constexpr int N4 = CPB * HW / 4;
    const float4* pp = (const float4*)p + ((size_t)b * C + (size_t)cg * CPB) * HW4;
    const float4* tt = (const float4*)t + ((size_t)b * C + (size_t)cg * CPB) * HW4;
    const float4* mm = (const float4*)s_mask;
    float acc = 0.0f;
    #pragma unroll 4
    for (int i = tid; i < N4; i += 256) {
        float4 pv = pp[i];
        float4 tv = tt[i];
        float4 mv = mm[i % HW4];
        float d0 = pv.x - tv.x, d1 = pv.y - tv.y;
        float d2 = pv.z - tv.z, d3 = pv.w - tv.w;
        acc += d0 * d0 * mv.x * mv.x + d1 * d1 * mv.y * mv.y
             + d2 * d2 * mv.z * mv.z + d3 * d3 * mv.w * mv.w;
    }

    float qb = block_reduce(acc);
    __syncthreads();
    float mb = block_reduce(cg == 0 ? msum : 0.0f);
    if (tid == 0) {
        g_part_sq[blockIdx.x] = (double)qb;
        g_part_m[blockIdx.x]  = (double)mb;
    }
}

// ---------------- finalize helper (inside the same kernel, last block) ----------------
__device__ __forceinline__ double sum_range_d(const double* a, int lo, int hi, double* sd) {
    double s = 0.0;
    for (int i = lo + threadIdx.x; i < hi; i += 256) s += a[i];
    sd[threadIdx.x] = s;
    __syncthreads();
    for (int o = 128; o > 0; o >>= 1) {
        if (threadIdx.x < o) sd[threadIdx.x] += sd[threadIdx.x + o];
        __syncthreads();
    }
    double r = sd[0];
    __syncthreads();
    return r;
}

// ---------------- the single kernel ----------------
__global__ void __launch_bounds__(256) fused_kernel(
    const float* __restrict__ p0, const float* __restrict__ t0,
    const float* __restrict__ p1, const float* __restrict__ t1,
    const float* __restrict__ p2, const float* __restrict__ t2,
    const float* __restrict__ bboxes, const int* __restrict__ bidx, int nbox,
    float* __restrict__ out)
{
    __shared__ __align__(16) float s_mask[80 * 80];   // 25.6KB, reused by all levels

    const int blk = blockIdx.x;
    if (blk < NB0) {
        level_work<80, 128, 8>(p0, t0, bboxes, bidx, nbox, blk / 16, blk % 16, s_mask);
    } else if (blk < NB0 + NB1) {
        const int l = blk - NB0;
        level_work<40, 256, 32>(p1, t1, bboxes, bidx, nbox, l / 8, l % 8, s_mask);
    } else {
        const int l = blk - (NB0 + NB1);
        level_work<20, 512, 128>(p2, t2, bboxes, bidx, nbox, l / 4, l % 4, s_mask);
    }

    // ---- last block finishes the reduction ----
    __shared__ bool is_last;
    __threadfence();
    if (threadIdx.x == 0) {
        int prev = atomicAdd(&g_counter, 1);
        is_last = (prev == NB_TOT - 1);
    }
    __syncthreads();
    if (!is_last) return;

    double* sd = (double*)s_mask;   // reuse smem (2KB needed)
    double q0 = sum_range_d(g_part_sq, 0, NB0, sd);
    double q1 = sum_range_d(g_part_sq, NB0, NB0 + NB1, sd);
    double q2 = sum_range_d(g_part_sq, NB0 + NB1, NB_TOT, sd);
    double m0 = sum_range_d(g_part_m, 0, NB0, sd);
    double m1 = sum_range_d(g_part_m, NB0, NB0 + NB1, sd);
    double m2 = sum_range_d(g_part_m, NB0 + NB1, NB_TOT, sd);
    if (threadIdx.x == 0) {
        double total = q0 / (128.0 * m0) + q1 / (256.0 * m1) + q2 / (512.0 * m2);
        out[0] = (float)(total / 3.0);
        g_counter = 0;   // reset for next (graph-replayed) call
    }
}

extern "C" void kernel_launch(void* const* d_in, const int* in_sizes, int n_in,
                              void* d_out, int out_size)
{
    // metadata order is INTERLEAVED: pred0, true0, pred1, true1, pred2, true2
    const float* p0 = (const float*)d_in[0];
    const float* t0 = (const float*)d_in[1];
    const float* p1 = (const float*)d_in[2];
    const float* t1 = (const float*)d_in[3];
    const float* p2 = (const float*)d_in[4];
    const float* t2 = (const float*)d_in[5];
    const float* bboxes = (const float*)d_in[6];
    const int* bidx = (const int*)d_in[8];
    const int nbox = in_sizes[8];
    float* out = (float*)d_out;

    fused_kernel<<<NB_TOT, 256>>>(p0, t0, p1, t1, p2, t2, bboxes, bidx, nbox, out);
}